// round 3
// baseline (speedup 1.0000x reference)
#include <cuda_runtime.h>
#include <cuda_bf16.h>

// Cosine similarity + segmented mean, one fused kernel.
// x1, x2: [N, 65536] fp32. out: [N/n] fp32.
//
// Geometry: 2 CTAs per sample (half-sample tiles of 8192 float4), 256
// threads/CTA -> 1024 CTAs = 6.92 waves of 8 CTAs/SM on 148 SMs; tail wave
// 92% full (vs 46% at 512x512). Last CTA (global counter) finalizes.

#define VEC_D        65536            // L*C
#define VEC_D4       (VEC_D / 4)      // 16384 float4 per sample
#define TILES_PER_S  2
#define TILE_D4      (VEC_D4 / TILES_PER_S)   // 8192 float4 per tile
#define T1           256              // threads per CTA
#define MAX_TILES    2048             // scratch capacity (N*2 = 1024 here)

__device__ float        g_dot[MAX_TILES];
__device__ float        g_n1[MAX_TILES];
__device__ float        g_n2[MAX_TILES];
__device__ unsigned int g_done;       // zero-init; reset by last CTA

__device__ __forceinline__ float warp_sum(float v) {
    #pragma unroll
    for (int off = 16; off > 0; off >>= 1)
        v += __shfl_xor_sync(0xFFFFFFFFu, v, off);
    return v;
}

__device__ __forceinline__ float4 ldcs4(const float4* p) {
    return __ldcs(p);                 // evict-first: zero-reuse stream
}

__global__ void __launch_bounds__(T1)
cos_fused(const float* __restrict__ x1, const float* __restrict__ x2,
          float* __restrict__ out, int n_per_group, int n_groups,
          int n_tiles) {
    const int tile = blockIdx.x;
    const size_t base = (size_t)tile * TILE_D4;
    const float4* __restrict__ a = reinterpret_cast<const float4*>(x1) + base;
    const float4* __restrict__ b = reinterpret_cast<const float4*>(x2) + base;

    float dot = 0.0f, n1 = 0.0f, n2 = 0.0f;

    // 8192 float4 / 256 threads = 32 iterations.
    #pragma unroll 4
    for (int i = threadIdx.x; i < TILE_D4; i += T1) {
        float4 av = ldcs4(a + i);
        float4 bv = ldcs4(b + i);
        dot = fmaf(av.x, bv.x, dot);
        dot = fmaf(av.y, bv.y, dot);
        dot = fmaf(av.z, bv.z, dot);
        dot = fmaf(av.w, bv.w, dot);
        n1  = fmaf(av.x, av.x, n1);
        n1  = fmaf(av.y, av.y, n1);
        n1  = fmaf(av.z, av.z, n1);
        n1  = fmaf(av.w, av.w, n1);
        n2  = fmaf(bv.x, bv.x, n2);
        n2  = fmaf(bv.y, bv.y, n2);
        n2  = fmaf(bv.z, bv.z, n2);
        n2  = fmaf(bv.w, bv.w, n2);
    }

    __shared__ float s_dot[T1 / 32];
    __shared__ float s_n1[T1 / 32];
    __shared__ float s_n2[T1 / 32];
    __shared__ bool  s_last;

    dot = warp_sum(dot);
    n1  = warp_sum(n1);
    n2  = warp_sum(n2);

    const int lane = threadIdx.x & 31;
    const int wid  = threadIdx.x >> 5;
    if (lane == 0) {
        s_dot[wid] = dot;
        s_n1[wid]  = n1;
        s_n2[wid]  = n2;
    }
    __syncthreads();

    if (wid == 0) {
        dot = (lane < T1 / 32) ? s_dot[lane] : 0.0f;
        n1  = (lane < T1 / 32) ? s_n1[lane]  : 0.0f;
        n2  = (lane < T1 / 32) ? s_n2[lane]  : 0.0f;
        dot = warp_sum(dot);
        n1  = warp_sum(n1);
        n2  = warp_sum(n2);
        if (lane == 0) {
            g_dot[tile] = dot;
            g_n1[tile]  = n1;
            g_n2[tile]  = n2;
            __threadfence();
            unsigned int prev = atomicAdd(&g_done, 1u);
            s_last = (prev == (unsigned int)(n_tiles - 1));
        }
    }
    __syncthreads();

    // Last CTA finalizes all groups deterministically.
    if (s_last) {
        __threadfence();
        for (int g = threadIdx.x; g < n_groups; g += T1) {
            float acc = 0.0f;
            for (int j = 0; j < n_per_group; j++) {
                const int s = g * n_per_group + j;
                float d = 0.0f, a2 = 0.0f, b2 = 0.0f;
                #pragma unroll
                for (int h = 0; h < TILES_PER_S; h++) {
                    const int t = s * TILES_PER_S + h;
                    d  += g_dot[t];
                    a2 += g_n1[t];
                    b2 += g_n2[t];
                }
                const float denom = sqrtf(a2) * sqrtf(b2);
                acc += d / fmaxf(denom, 1e-8f);
            }
            out[g] = acc / (float)n_per_group;
        }
        if (threadIdx.x == 0) g_done = 0;   // reset for next graph replay
    }
}

extern "C" void kernel_launch(void* const* d_in, const int* in_sizes, int n_in,
                              void* d_out, int out_size) {
    const float* x1 = (const float*)d_in[0];
    const float* x2 = (const float*)d_in[1];
    const int N = in_sizes[0] / VEC_D;        // 512 samples
    const int n_groups = out_size;            // 64
    const int n_per_group = N / n_groups;     // 8
    const int n_tiles = N * TILES_PER_S;      // 1024 CTAs
    float* out = (float*)d_out;

    cos_fused<<<n_tiles, T1>>>(x1, x2, out, n_per_group, n_groups, n_tiles);
}

// round 4
// speedup vs baseline: 1.0014x; 1.0014x over previous
#include <cuda_runtime.h>
#include <cuda_bf16.h>

// Cosine similarity + segmented mean, two kernels with PDL overlap.
// x1, x2: [N, 65536] fp32. out: [N/n] fp32.
//
// Stage1: 2 CTAs per sample (8192 float4 tiles), 256 threads. Inner loop
// front-batches 8x LDG.128 (4 per stream) before any FMA -> MLP_p1=8 per
// warp (R2/R3 compiled to MLP~2 at regs=32 and plateaued at 6.0 TB/s).
// Stage2: 64 threads, launched with programmatic dependent launch so its
// launch latency hides under stage1's tail.

#define VEC_D     65536             // L*C
#define VEC_D4    (VEC_D / 4)       // 16384 float4 per sample
#define TILE_D4   8192              // half-sample tile
#define T1        256
#define BATCH     (4 * T1)          // 1024 float4 per batch
#define NBATCH    (TILE_D4 / BATCH) // 8
#define MAX_TILES 2048

__device__ float g_dot[MAX_TILES];
__device__ float g_n1[MAX_TILES];
__device__ float g_n2[MAX_TILES];

__device__ __forceinline__ float warp_sum(float v) {
    #pragma unroll
    for (int off = 16; off > 0; off >>= 1)
        v += __shfl_xor_sync(0xFFFFFFFFu, v, off);
    return v;
}

__device__ __forceinline__ void fma3(const float4& av, const float4& bv,
                                     float& dot, float& n1, float& n2) {
    dot = fmaf(av.x, bv.x, dot); dot = fmaf(av.y, bv.y, dot);
    dot = fmaf(av.z, bv.z, dot); dot = fmaf(av.w, bv.w, dot);
    n1  = fmaf(av.x, av.x, n1);  n1  = fmaf(av.y, av.y, n1);
    n1  = fmaf(av.z, av.z, n1);  n1  = fmaf(av.w, av.w, n1);
    n2  = fmaf(bv.x, bv.x, n2);  n2  = fmaf(bv.y, bv.y, n2);
    n2  = fmaf(bv.z, bv.z, n2);  n2  = fmaf(bv.w, bv.w, n2);
}

__global__ void __launch_bounds__(T1, 4)
cos_stage1(const float* __restrict__ x1, const float* __restrict__ x2) {
    // Allow PDL-secondary to begin launching immediately.
    cudaTriggerProgrammaticLaunchCompletion();

    const int tile = blockIdx.x;
    const size_t base = (size_t)tile * TILE_D4;
    const float4* __restrict__ a = reinterpret_cast<const float4*>(x1) + base;
    const float4* __restrict__ b = reinterpret_cast<const float4*>(x2) + base;

    float dot = 0.0f, n1 = 0.0f, n2 = 0.0f;

    #pragma unroll 1
    for (int it = 0; it < NBATCH; it++) {
        const int i = it * BATCH + threadIdx.x;
        // Front-batch 8 independent 128-bit loads (MLP_p1 = 8).
        float4 av0 = __ldcs(a + i);
        float4 av1 = __ldcs(a + i + T1);
        float4 av2 = __ldcs(a + i + 2 * T1);
        float4 av3 = __ldcs(a + i + 3 * T1);
        float4 bv0 = __ldcs(b + i);
        float4 bv1 = __ldcs(b + i + T1);
        float4 bv2 = __ldcs(b + i + 2 * T1);
        float4 bv3 = __ldcs(b + i + 3 * T1);
        fma3(av0, bv0, dot, n1, n2);
        fma3(av1, bv1, dot, n1, n2);
        fma3(av2, bv2, dot, n1, n2);
        fma3(av3, bv3, dot, n1, n2);
    }

    __shared__ float s_dot[T1 / 32];
    __shared__ float s_n1[T1 / 32];
    __shared__ float s_n2[T1 / 32];

    dot = warp_sum(dot);
    n1  = warp_sum(n1);
    n2  = warp_sum(n2);

    const int lane = threadIdx.x & 31;
    const int wid  = threadIdx.x >> 5;
    if (lane == 0) { s_dot[wid] = dot; s_n1[wid] = n1; s_n2[wid] = n2; }
    __syncthreads();

    if (wid == 0) {
        dot = (lane < T1 / 32) ? s_dot[lane] : 0.0f;
        n1  = (lane < T1 / 32) ? s_n1[lane]  : 0.0f;
        n2  = (lane < T1 / 32) ? s_n2[lane]  : 0.0f;
        dot = warp_sum(dot);
        n1  = warp_sum(n1);
        n2  = warp_sum(n2);
        if (lane == 0) {
            g_dot[tile] = dot;
            g_n1[tile]  = n1;
            g_n2[tile]  = n2;
        }
    }
}

// PDL secondary: waits for stage1 grid completion, then finalizes.
__global__ void cos_stage2(float* __restrict__ out, int n_per_group,
                           int n_groups) {
    cudaGridDependencySynchronize();
    const int g = blockIdx.x * blockDim.x + threadIdx.x;
    if (g >= n_groups) return;
    float acc = 0.0f;
    for (int j = 0; j < n_per_group; j++) {
        const int s = g * n_per_group + j;
        const float d  = g_dot[2 * s] + g_dot[2 * s + 1];
        const float a2 = g_n1[2 * s]  + g_n1[2 * s + 1];
        const float b2 = g_n2[2 * s]  + g_n2[2 * s + 1];
        acc += d / fmaxf(sqrtf(a2) * sqrtf(b2), 1e-8f);
    }
    out[g] = acc / (float)n_per_group;
}

extern "C" void kernel_launch(void* const* d_in, const int* in_sizes, int n_in,
                              void* d_out, int out_size) {
    const float* x1 = (const float*)d_in[0];
    const float* x2 = (const float*)d_in[1];
    const int N = in_sizes[0] / VEC_D;        // 512 samples
    const int n_groups = out_size;            // 64
    const int n_per_group = N / n_groups;     // 8
    const int n_tiles = N * 2;                // 1024 CTAs
    float* out = (float*)d_out;

    cos_stage1<<<n_tiles, T1>>>(x1, x2);

    // Stage2 with programmatic dependent launch (overlaps launch latency).
    cudaLaunchAttribute attr;
    attr.id = cudaLaunchAttributeProgrammaticStreamSerialization;
    attr.val.programmaticStreamSerializationAllowed = 1;
    cudaLaunchConfig_t cfg = {};
    cfg.gridDim  = dim3(1, 1, 1);
    cfg.blockDim = dim3(64, 1, 1);
    cfg.dynamicSmemBytes = 0;
    cfg.stream = 0;
    cfg.attrs = &attr;
    cfg.numAttrs = 1;
    cudaLaunchKernelEx(&cfg, cos_stage2, out, n_per_group, n_groups);
}

// round 5
// speedup vs baseline: 1.0323x; 1.0309x over previous
#include <cuda_runtime.h>
#include <cuda_bf16.h>

// Cosine similarity + segmented mean.
// x1, x2: [N, 65536] fp32. out: [N/n] fp32.
//
// Stage1 = R1's empirically fastest config (512 CTAs x 512 threads, plain
// unroll-4 loop): every loop/geometry variant tried (R2-R4) landed at the
// same ~6.0 TB/s HBM plateau, so this loop is at the memory-system ceiling.
// Stage2 finalize uses programmatic dependent launch so its launch latency
// overlaps stage1's tail wave instead of serializing after it.

#define VEC_D       65536           // L*C
#define VEC_D4      (VEC_D / 4)     // float4 per sample = 16384
#define T1          512             // threads per CTA in stage 1
#define MAX_SAMPLES 1024            // scratch capacity (N = 512 here)

__device__ float g_dot[MAX_SAMPLES];
__device__ float g_n1[MAX_SAMPLES];
__device__ float g_n2[MAX_SAMPLES];

__device__ __forceinline__ float warp_sum(float v) {
    #pragma unroll
    for (int off = 16; off > 0; off >>= 1)
        v += __shfl_xor_sync(0xFFFFFFFFu, v, off);
    return v;
}

__global__ void __launch_bounds__(T1)
cos_stage1(const float* __restrict__ x1, const float* __restrict__ x2) {
    const int s = blockIdx.x;
    const float4* __restrict__ a =
        reinterpret_cast<const float4*>(x1) + (size_t)s * VEC_D4;
    const float4* __restrict__ b =
        reinterpret_cast<const float4*>(x2) + (size_t)s * VEC_D4;

    float dot = 0.0f, n1 = 0.0f, n2 = 0.0f;

    // 16384 float4 / 512 threads = 32 iterations. (R1 schedule — fastest.)
    #pragma unroll 4
    for (int i = threadIdx.x; i < VEC_D4; i += T1) {
        float4 av = a[i];
        float4 bv = b[i];
        dot = fmaf(av.x, bv.x, dot);
        dot = fmaf(av.y, bv.y, dot);
        dot = fmaf(av.z, bv.z, dot);
        dot = fmaf(av.w, bv.w, dot);
        n1  = fmaf(av.x, av.x, n1);
        n1  = fmaf(av.y, av.y, n1);
        n1  = fmaf(av.z, av.z, n1);
        n1  = fmaf(av.w, av.w, n1);
        n2  = fmaf(bv.x, bv.x, n2);
        n2  = fmaf(bv.y, bv.y, n2);
        n2  = fmaf(bv.z, bv.z, n2);
        n2  = fmaf(bv.w, bv.w, n2);
    }

    __shared__ float s_dot[T1 / 32];
    __shared__ float s_n1[T1 / 32];
    __shared__ float s_n2[T1 / 32];

    dot = warp_sum(dot);
    n1  = warp_sum(n1);
    n2  = warp_sum(n2);

    const int lane = threadIdx.x & 31;
    const int wid  = threadIdx.x >> 5;
    if (lane == 0) {
        s_dot[wid] = dot;
        s_n1[wid]  = n1;
        s_n2[wid]  = n2;
    }
    __syncthreads();

    if (wid == 0) {
        dot = (lane < T1 / 32) ? s_dot[lane] : 0.0f;
        n1  = (lane < T1 / 32) ? s_n1[lane]  : 0.0f;
        n2  = (lane < T1 / 32) ? s_n2[lane]  : 0.0f;
        dot = warp_sum(dot);
        n1  = warp_sum(n1);
        n2  = warp_sum(n2);
        if (lane == 0) {
            g_dot[s] = dot;
            g_n1[s]  = n1;
            g_n2[s]  = n2;
        }
    }
    __syncthreads();
    // Partials written; allow the PDL secondary to begin launching.
    // (gridDependencySynchronize in stage2 still waits for ALL CTAs to
    // reach this point, and writes before the trigger are visible.)
    cudaTriggerProgrammaticLaunchCompletion();
}

// PDL secondary: launch overlaps stage1 tail; sync before reading partials.
__global__ void cos_stage2(float* __restrict__ out, int n_per_group,
                           int n_groups) {
    cudaGridDependencySynchronize();
    const int g = blockIdx.x * blockDim.x + threadIdx.x;
    if (g >= n_groups) return;
    float acc = 0.0f;
    for (int j = 0; j < n_per_group; j++) {
        const int s = g * n_per_group + j;
        const float denom = sqrtf(g_n1[s]) * sqrtf(g_n2[s]);
        acc += g_dot[s] / fmaxf(denom, 1e-8f);
    }
    out[g] = acc / (float)n_per_group;
}

extern "C" void kernel_launch(void* const* d_in, const int* in_sizes, int n_in,
                              void* d_out, int out_size) {
    const float* x1 = (const float*)d_in[0];
    const float* x2 = (const float*)d_in[1];
    const int N = in_sizes[0] / VEC_D;        // 512 samples
    const int n_groups = out_size;            // 64
    const int n_per_group = N / n_groups;     // 8
    float* out = (float*)d_out;

    cos_stage1<<<N, T1>>>(x1, x2);

    cudaLaunchAttribute attr;
    attr.id = cudaLaunchAttributeProgrammaticStreamSerialization;
    attr.val.programmaticStreamSerializationAllowed = 1;
    cudaLaunchConfig_t cfg = {};
    cfg.gridDim  = dim3(1, 1, 1);
    cfg.blockDim = dim3(64, 1, 1);
    cfg.dynamicSmemBytes = 0;
    cfg.stream = 0;
    cfg.attrs = &attr;
    cfg.numAttrs = 1;
    cudaLaunchKernelEx(&cfg, cos_stage2, out, n_per_group, n_groups);
}